// round 3
// baseline (speedup 1.0000x reference)
#include <cuda_runtime.h>
#include <math.h>

#define BATCH   16
#define T       640
#define EMBD    256
#define HEADS   8
#define DHDIM   32
#define BHDIM   128      // BATCH*HEADS
#define NHASH   8
#define NCHUNK  80
#define NROWS   10240    // BATCH*T

// ---------------- packed fp32 FFMA2 helpers ----------------
typedef unsigned long long u64t;

__device__ __forceinline__ u64t bcast2(float x){
  u64t r; asm("mov.b64 %0, {%1,%1};" : "=l"(r) : "f"(x)); return r;
}
__device__ __forceinline__ void fma2(u64t &acc, u64t a, u64t b){
  asm("fma.rn.f32x2 %0, %1, %2, %3;" : "=l"(acc) : "l"(a), "l"(b), "l"(acc));
}
__device__ __forceinline__ float2 unpack2(u64t v){
  float lo, hi; asm("mov.b64 {%0,%1}, %2;" : "=f"(lo), "=f"(hi) : "l"(v));
  return make_float2(lo, hi);
}

// ---------------- scratch (device globals; no allocation allowed) ----------------
__device__ float g_tokens[NROWS*EMBD];
__device__ float g_qk[BHDIM*T*DHDIM];
__device__ float g_v [BHDIM*T*DHDIM];
__device__ int   g_bucket[BHDIM*NHASH*T];
__device__ int   g_sorted[BHDIM*NHASH*T];
__device__ float g_ohash[(size_t)BHDIM*NHASH*T*DHDIM];
__device__ float g_logit[BHDIM*NHASH*T];
__device__ float g_omerged[NROWS*EMBD];

// ---------------- stage 1: maxpool + Haar DWT -> tokens ----------------
__global__ void frontend_kernel(const float* __restrict__ x){
  int idx = blockIdx.x*blockDim.x + threadIdx.x;
  if (idx >= BATCH*640*256) return;
  int p = idx & 255;
  int n = (idx >> 8) % 640;
  int b = idx / (640*256);
  int i = p >> 4, j = p & 15;
  float val;
  if (n < 128){
    const float* xp = x + (size_t)(b*128+n)*1024;
    float m = -INFINITY;
    int r0 = 2*i-1, c0 = 2*j-1;
    #pragma unroll
    for (int dr=0;dr<3;dr++){
      int r = r0+dr; if (r<0 || r>31) continue;
      #pragma unroll
      for (int dc=0;dc<3;dc++){
        int cc = c0+dc; if (cc<0 || cc>31) continue;
        m = fmaxf(m, xp[r*32+cc]);
      }
    }
    val = m;
  } else {
    int g  = (n-128)>>7;
    int ch = (n-128)&127;
    const float* xp = x + (size_t)(b*128+ch)*1024;
    float a  = xp[(2*i)*32 + 2*j];
    float bb = xp[(2*i)*32 + 2*j+1];
    float c  = xp[(2*i+1)*32 + 2*j];
    float d  = xp[(2*i+1)*32 + 2*j+1];
    if      (g==0) val = (a+bb+c+d)*0.5f;
    else if (g==1) val = (a-bb+c-d)*0.5f;
    else if (g==2) val = (a+bb-c-d)*0.5f;
    else           val = (a-bb-c+d)*0.5f;
  }
  g_tokens[idx] = val;
}

// ---------------- stage 2: fused qk/v GEMM (FFMA2), head-split epilogue ----------------
__global__ __launch_bounds__(256) void gemm_qkv_kernel(const float* __restrict__ Wqk,
                                                       const float* __restrict__ Wv){
  __shared__ float As [32][64];
  __shared__ float B1s[32][64];
  __shared__ float B2s[32][64];
  int tid = threadIdx.x;
  int m0 = blockIdx.y*64, n0 = blockIdx.x*64;
  int ty = tid>>4, tx = tid&15;
  u64t acc1[4][2], acc2[4][2];
  #pragma unroll
  for (int i=0;i<4;i++)
    #pragma unroll
    for (int j=0;j<2;j++){ acc1[i][j]=0ull; acc2[i][j]=0ull; }

  for (int k0=0;k0<256;k0+=32){
    int am = tid>>2, akq = tid&3;
    const float* asrc = g_tokens + (size_t)(m0+am)*256 + k0 + akq*8;
    float4 a0 = *(const float4*)asrc;
    float4 a1 = *(const float4*)(asrc+4);
    As[akq*8+0][am]=a0.x; As[akq*8+1][am]=a0.y; As[akq*8+2][am]=a0.z; As[akq*8+3][am]=a0.w;
    As[akq*8+4][am]=a1.x; As[akq*8+5][am]=a1.y; As[akq*8+6][am]=a1.z; As[akq*8+7][am]=a1.w;

    int bk = tid>>3, bnq = tid&7;
    const float* b1src = Wqk + (size_t)(k0+bk)*256 + n0 + bnq*8;
    const float* b2src = Wv  + (size_t)(k0+bk)*256 + n0 + bnq*8;
    *(float4*)&B1s[bk][bnq*8]   = *(const float4*)b1src;
    *(float4*)&B1s[bk][bnq*8+4] = *(const float4*)(b1src+4);
    *(float4*)&B2s[bk][bnq*8]   = *(const float4*)b2src;
    *(float4*)&B2s[bk][bnq*8+4] = *(const float4*)(b2src+4);
    __syncthreads();

    #pragma unroll
    for (int k=0;k<32;k++){
      float4 av = *(float4*)&As [k][ty*4];
      ulonglong2 b1 = *(ulonglong2*)&B1s[k][tx*4];
      ulonglong2 b2 = *(ulonglong2*)&B2s[k][tx*4];
      float aa[4] = {av.x,av.y,av.z,av.w};
      #pragma unroll
      for (int i2=0;i2<4;i2++){
        u64t ab = bcast2(aa[i2]);
        fma2(acc1[i2][0], ab, b1.x); fma2(acc1[i2][1], ab, b1.y);
        fma2(acc2[i2][0], ab, b2.x); fma2(acc2[i2][1], ab, b2.y);
      }
    }
    __syncthreads();
  }
  #pragma unroll
  for (int i2=0;i2<4;i2++){
    int row = m0 + ty*4 + i2;
    int b = row/640, tok = row%640;
    float r1[4], r2[4];
    float2 t;
    t = unpack2(acc1[i2][0]); r1[0]=t.x; r1[1]=t.y;
    t = unpack2(acc1[i2][1]); r1[2]=t.x; r1[3]=t.y;
    t = unpack2(acc2[i2][0]); r2[0]=t.x; r2[1]=t.y;
    t = unpack2(acc2[i2][1]); r2[2]=t.x; r2[3]=t.y;
    #pragma unroll
    for (int j2=0;j2<4;j2++){
      int col = n0 + tx*4 + j2;
      int head = col>>5, dh = col&31;
      size_t o = ((size_t)(b*8+head)*640 + tok)*32 + dh;
      g_qk[o] = r1[j2];
      g_v [o] = r2[j2];
    }
  }
}

// ---------------- stage 3a: LSH bucket ids ----------------
__global__ void bucket_kernel(const float* __restrict__ rot){
  __shared__ float s_rot[32*NHASH*5];
  for (int i=threadIdx.x;i<1280;i+=blockDim.x) s_rot[i]=rot[i];
  __syncthreads();
  int idx = blockIdx.x*blockDim.x + threadIdx.x;
  if (idx >= BHDIM*NHASH*T) return;
  int pos = idx % 640;
  int h   = (idx/640) & 7;
  int bh  = idx / (NHASH*T);
  const float* q = g_qk + ((size_t)bh*640 + pos)*32;
  float r[5] = {0.f,0.f,0.f,0.f,0.f};
  #pragma unroll 8
  for (int f=0;f<32;f++){
    float qf = q[f];
    const float* rp = s_rot + f*40 + h*5;
    #pragma unroll
    for (int i=0;i<5;i++) r[i] += qf*rp[i];
  }
  float best = r[0]; int bi = 0;
  #pragma unroll
  for (int i=1;i<5;i++) if (r[i] > best){ best=r[i]; bi=i; }
  #pragma unroll
  for (int i=0;i<5;i++){ float v = -r[i]; if (v > best){ best=v; bi=5+i; } }
  g_bucket[idx] = bi;
}

// ---------------- stage 3b: stable counting sort per (bh, hash) ----------------
__global__ __launch_bounds__(320) void sort_kernel(){
  __shared__ int cnt[10], off[10];
  int bhh = blockIdx.x;
  const int* bk = g_bucket + bhh*640;
  int w = threadIdx.x>>5, lane = threadIdx.x&31;
  int count = 0;
  for (int base=0;base<640;base+=32){
    int bb = bk[base+lane];
    unsigned mask = __ballot_sync(0xffffffffu, bb==w);
    count += __popc(mask);
  }
  if (lane==0) cnt[w] = count;
  __syncthreads();
  if (threadIdx.x==0){
    int run=0;
    for (int b=0;b<10;b++){ off[b]=run; run+=cnt[b]; }
  }
  __syncthreads();
  int base_off = off[w]; int run = 0;
  int* out = g_sorted + bhh*640;
  for (int base=0;base<640;base+=32){
    int bb = bk[base+lane];
    unsigned mask = __ballot_sync(0xffffffffu, bb==w);
    if (bb==w){
      int slot = base_off + run + __popc(mask & ((1u<<lane)-1u));
      out[slot] = base+lane;
    }
    run += __popc(mask);
  }
}

// ---------------- stage 4: chunked attention, register-tiled + FFMA2 ----------------
#define QT_PAD 68
#define KT_PAD 132
#define P_PAD  132
#define SMEM_ATTN ((64*P_PAD + 128*32)*4 + (64+128)*4)

__global__ __launch_bounds__(256) void attn_kernel(){
  extern __shared__ char smem_raw[];
  float* s_p  = (float*)smem_raw;            // [64][132]
  float* s_qT = s_p;                         // [32][68]   (aliased)
  float* s_kT = s_qT + 32*QT_PAD;            // [32][132]  (aliased)
  float* s_v  = s_p + 64*P_PAD;              // [128][32]
  int*   s_qt = (int*)(s_v + 128*32);        // [64]
  int*   s_kt = s_qt + 64;                   // [128]

  int tid = threadIdx.x;
  int blk = blockIdx.x;
  int bh = blk / NCHUNK, c = blk % NCHUNK;
  int h  = c / 10;
  int pc = (c + NCHUNK - 1) % NCHUNK;
  int ph = pc / 10;
  const int* sortedbh = g_sorted + bh*NHASH*T;

  if (tid < 64)
    s_qt[tid] = sortedbh[h*640 + (c%10)*64 + tid];
  else if (tid < 192){
    int j = tid - 64;
    s_kt[j] = (j < 64) ? sortedbh[h*640 + (c%10)*64 + j]
                       : sortedbh[ph*640 + (pc%10)*64 + (j-64)];
  }
  __syncthreads();

  // Load Q feature-major
  {
    int i = tid >> 2, f = (tid & 3) * 8;
    const float* src = g_qk + ((size_t)bh*640 + s_qt[i])*32 + f;
    float4 a = *(const float4*)src;
    float4 b = *(const float4*)(src+4);
    s_qT[(f+0)*QT_PAD+i]=a.x; s_qT[(f+1)*QT_PAD+i]=a.y;
    s_qT[(f+2)*QT_PAD+i]=a.z; s_qT[(f+3)*QT_PAD+i]=a.w;
    s_qT[(f+4)*QT_PAD+i]=b.x; s_qT[(f+5)*QT_PAD+i]=b.y;
    s_qT[(f+6)*QT_PAD+i]=b.z; s_qT[(f+7)*QT_PAD+i]=b.w;
  }
  // Load K feature-major + normalize
  {
    int j = tid >> 1, fh = (tid & 1) * 16;
    const float* src = g_qk + ((size_t)bh*640 + s_kt[j])*32 + fh;
    float buf[16]; float ss = 0.f;
    #pragma unroll
    for (int u=0;u<16;u+=4){
      float4 a = *(const float4*)(src+u);
      buf[u]=a.x; buf[u+1]=a.y; buf[u+2]=a.z; buf[u+3]=a.w;
      ss += a.x*a.x + a.y*a.y + a.z*a.z + a.w*a.w;
    }
    ss += __shfl_xor_sync(0xffffffffu, ss, 1);
    float inv = 1.f / fmaxf(sqrtf(ss), 1e-6f);
    #pragma unroll
    for (int u=0;u<16;u++) s_kT[(fh+u)*KT_PAD + j] = buf[u]*inv;
  }
  // Load V row-major
  {
    int j = tid >> 1, fh = (tid & 1) * 16;
    const float* src = g_v + ((size_t)bh*640 + s_kt[j])*32 + fh;
    float* dst = s_v + j*32 + fh;
    #pragma unroll
    for (int u=0;u<16;u+=4) *(float4*)(dst+u) = *(const float4*)(src+u);
  }
  __syncthreads();

  // ---- dots microkernel: 64x128x32, thread tile 4x8, FFMA2 packed over j ----
  int ty = tid >> 4, tx = tid & 15;   // i0 = ty*4, j0 = tx*8
  u64t acc2[4][4];
  #pragma unroll
  for (int a=0;a<4;a++)
    #pragma unroll
    for (int b=0;b<4;b++) acc2[a][b]=0ull;

  #pragma unroll 8
  for (int k=0;k<32;k++){
    float4 q  = *(float4*)&s_qT[k*QT_PAD + ty*4];
    ulonglong2 kb0 = *(ulonglong2*)&s_kT[k*KT_PAD + tx*8];
    ulonglong2 kb1 = *(ulonglong2*)&s_kT[k*KT_PAD + tx*8 + 4];
    float qa[4] = {q.x,q.y,q.z,q.w};
    #pragma unroll
    for (int a=0;a<4;a++){
      u64t qb = bcast2(qa[a]);
      fma2(acc2[a][0], qb, kb0.x); fma2(acc2[a][1], qb, kb0.y);
      fma2(acc2[a][2], qb, kb1.x); fma2(acc2[a][3], qb, kb1.y);
    }
  }

  // unpack, scale + self-mask
  float acc[4][8];
  #pragma unroll
  for (int a=0;a<4;a++)
    #pragma unroll
    for (int b=0;b<4;b++){
      float2 t = unpack2(acc2[a][b]);
      acc[a][2*b]=t.x; acc[a][2*b+1]=t.y;
    }
  int qtok[4], ktok[8];
  #pragma unroll
  for (int a=0;a<4;a++) qtok[a] = s_qt[ty*4+a];
  #pragma unroll
  for (int b=0;b<8;b++) ktok[b] = s_kt[tx*8+b];
  #pragma unroll
  for (int a=0;a<4;a++)
    #pragma unroll
    for (int b=0;b<8;b++){
      float d = acc[a][b]*0.17677669529663687f;
      acc[a][b] = (ktok[b]==qtok[a]) ? -50000.f : d;
    }

  // row softmax over 128 cols (reduce across tx group of 16 lanes)
  float lse[4];
  #pragma unroll
  for (int a=0;a<4;a++){
    float m = acc[a][0];
    #pragma unroll
    for (int b=1;b<8;b++) m = fmaxf(m, acc[a][b]);
    #pragma unroll
    for (int o=8;o>0;o>>=1) m = fmaxf(m, __shfl_xor_sync(0xffffffffu, m, o, 16));
    float s = 0.f;
    #pragma unroll
    for (int b=0;b<8;b++) s += __expf(acc[a][b]-m);
    #pragma unroll
    for (int o=8;o>0;o>>=1) s += __shfl_xor_sync(0xffffffffu, s, o, 16);
    lse[a] = m + __logf(s);
  }
  if (tx == 0){
    #pragma unroll
    for (int a=0;a<4;a++)
      g_logit[(bh*NHASH+h)*T + qtok[a]] = lse[a];
  }

  __syncthreads();   // dots reads of s_qT/s_kT done before s_p overwrite

  #pragma unroll
  for (int a=0;a<4;a++){
    float4 p0, p1;
    p0.x=__expf(acc[a][0]-lse[a]); p0.y=__expf(acc[a][1]-lse[a]);
    p0.z=__expf(acc[a][2]-lse[a]); p0.w=__expf(acc[a][3]-lse[a]);
    p1.x=__expf(acc[a][4]-lse[a]); p1.y=__expf(acc[a][5]-lse[a]);
    p1.z=__expf(acc[a][6]-lse[a]); p1.w=__expf(acc[a][7]-lse[a]);
    *(float4*)&s_p[(ty*4+a)*P_PAD + tx*8]     = p0;
    *(float4*)&s_p[(ty*4+a)*P_PAD + tx*8 + 4] = p1;
  }
  __syncthreads();

  // ---- PV: 64x32x128, all 256 threads (thread = row i x d-octet), FFMA2 over d ----
  {
    int i  = tid >> 2;           // 0..63
    int d0 = (tid & 3) * 8;      // 0,8,16,24
    u64t o[4] = {0ull,0ull,0ull,0ull};
    const float* pr = s_p + i*P_PAD;
    #pragma unroll 4
    for (int j=0;j<128;j++){
      u64t pb = bcast2(pr[j]);
      ulonglong2 v0 = *(ulonglong2*)&s_v[j*32 + d0];
      ulonglong2 v1 = *(ulonglong2*)&s_v[j*32 + d0 + 4];
      fma2(o[0], pb, v0.x); fma2(o[1], pb, v0.y);
      fma2(o[2], pb, v1.x); fma2(o[3], pb, v1.y);
    }
    float2 t0 = unpack2(o[0]), t1 = unpack2(o[1]);
    float2 t2 = unpack2(o[2]), t3 = unpack2(o[3]);
    float* dst = g_ohash + ((size_t)(bh*NHASH+h)*T + s_qt[i])*32 + d0;
    *(float4*)dst     = make_float4(t0.x,t0.y,t1.x,t1.y);
    *(float4*)(dst+4) = make_float4(t2.x,t2.y,t3.x,t3.y);
  }
}

// ---------------- stage 5: combine hashes, merge heads (float4) ----------------
__global__ void combine_kernel(){
  int idx = blockIdx.x*blockDim.x + threadIdx.x;
  if (idx >= BHDIM*T*8) return;
  int dq  = idx & 7;
  int pos = (idx >> 3) % 640;
  int bh  = idx / (640*8);
  float l[NHASH];
  #pragma unroll
  for (int h=0;h<NHASH;h++) l[h] = g_logit[(bh*NHASH+h)*T + pos];
  float m = l[0];
  #pragma unroll
  for (int h=1;h<NHASH;h++) m = fmaxf(m, l[h]);
  float s = 0.f;
  float e[NHASH];
  #pragma unroll
  for (int h=0;h<NHASH;h++){ e[h] = __expf(l[h]-m); s += e[h]; }
  float inv = 1.f/s;
  float4 acc = make_float4(0.f,0.f,0.f,0.f);
  #pragma unroll
  for (int h=0;h<NHASH;h++){
    float w = e[h]*inv;
    float4 v = *(const float4*)(g_ohash + ((size_t)(bh*NHASH+h)*T + pos)*32 + dq*4);
    acc.x += w*v.x; acc.y += w*v.y; acc.z += w*v.z; acc.w += w*v.w;
  }
  int b = bh>>3, head = bh&7;
  *(float4*)(g_omerged + ((size_t)b*640 + pos)*256 + head*32 + dq*4) = acc;
}

// ---------------- stage 6: output GEMM + bias (FFMA2) ----------------
__global__ __launch_bounds__(256) void gemm_out_kernel(const float* __restrict__ W,
                                                       const float* __restrict__ bias,
                                                       float* __restrict__ out){
  __shared__ float As[32][64];
  __shared__ float Bs[32][64];
  int tid = threadIdx.x;
  int m0 = blockIdx.y*64, n0 = blockIdx.x*64;
  int ty = tid>>4, tx = tid&15;
  u64t acc[4][2];
  #pragma unroll
  for (int i=0;i<4;i++){ acc[i][0]=0ull; acc[i][1]=0ull; }

  for (int k0=0;k0<256;k0+=32){
    int am = tid>>2, akq = tid&3;
    const float* asrc = g_omerged + (size_t)(m0+am)*256 + k0 + akq*8;
    float4 a0 = *(const float4*)asrc;
    float4 a1 = *(const float4*)(asrc+4);
    As[akq*8+0][am]=a0.x; As[akq*8+1][am]=a0.y; As[akq*8+2][am]=a0.z; As[akq*8+3][am]=a0.w;
    As[akq*8+4][am]=a1.x; As[akq*8+5][am]=a1.y; As[akq*8+6][am]=a1.z; As[akq*8+7][am]=a1.w;

    int bk = tid>>3, bnq = tid&7;
    const float* bsrc = W + (size_t)(k0+bk)*256 + n0 + bnq*8;
    *(float4*)&Bs[bk][bnq*8]   = *(const float4*)bsrc;
    *(float4*)&Bs[bk][bnq*8+4] = *(const float4*)(bsrc+4);
    __syncthreads();

    #pragma unroll
    for (int k=0;k<32;k++){
      float4 av = *(float4*)&As[k][ty*4];
      ulonglong2 bv = *(ulonglong2*)&Bs[k][tx*4];
      float aa[4] = {av.x,av.y,av.z,av.w};
      #pragma unroll
      for (int i2=0;i2<4;i2++){
        u64t ab = bcast2(aa[i2]);
        fma2(acc[i2][0], ab, bv.x);
        fma2(acc[i2][1], ab, bv.y);
      }
    }
    __syncthreads();
  }
  #pragma unroll
  for (int i2=0;i2<4;i2++){
    int row = m0 + ty*4 + i2;
    float2 t0 = unpack2(acc[i2][0]);
    float2 t1 = unpack2(acc[i2][1]);
    float r[4] = {t0.x,t0.y,t1.x,t1.y};
    #pragma unroll
    for (int j2=0;j2<4;j2++){
      int col = n0 + tx*4 + j2;
      out[(size_t)row*256 + col] = r[j2] + bias[col];
    }
  }
}

// ---------------- launch ----------------
extern "C" void kernel_launch(void* const* d_in, const int* in_sizes, int n_in,
                              void* d_out, int out_size){
  const float* x     = (const float*)d_in[0];
  const float* w_qk  = (const float*)d_in[1];
  const float* w_v   = (const float*)d_in[2];
  const float* w_out = (const float*)d_in[3];
  const float* b_out = (const float*)d_in[4];
  const float* rot   = (const float*)d_in[5];
  float* out = (float*)d_out;

  frontend_kernel<<<(BATCH*640*256+255)/256, 256>>>(x);
  gemm_qkv_kernel<<<dim3(4,160), 256>>>(w_qk, w_v);
  bucket_kernel<<<(BHDIM*NHASH*T+255)/256, 256>>>(rot);
  sort_kernel<<<BHDIM*NHASH, 320>>>();
  cudaFuncSetAttribute(attn_kernel, cudaFuncAttributeMaxDynamicSharedMemorySize, SMEM_ATTN);
  attn_kernel<<<BHDIM*NCHUNK, 256, SMEM_ATTN>>>();
  combine_kernel<<<(BHDIM*T*8+255)/256, 256>>>();
  gemm_out_kernel<<<dim3(4,160), 256>>>(w_out, b_out, out);
}

// round 4
// speedup vs baseline: 1.8815x; 1.8815x over previous
#include <cuda_runtime.h>
#include <math.h>

#define BATCH   16
#define T       640
#define EMBD    256
#define HEADS   8
#define DHDIM   32
#define BHDIM   128      // BATCH*HEADS
#define NHASH   8
#define NCHUNK  80
#define NROWS   10240    // BATCH*T

// ---------------- scratch (device globals; no allocation allowed) ----------------
__device__ float g_tokens[NROWS*EMBD];
__device__ float g_qk[BHDIM*T*DHDIM];
__device__ float g_v [BHDIM*T*DHDIM];
__device__ int   g_bucket[BHDIM*NHASH*T];
__device__ int   g_sorted[BHDIM*NHASH*T];
__device__ float g_ohash[(size_t)BHDIM*NHASH*T*DHDIM];
__device__ float g_logit[BHDIM*NHASH*T];
__device__ float g_omerged[NROWS*EMBD];

// ---------------- tf32 mma.sync helper ----------------
__device__ __forceinline__ void mma_tf32(float* d, const unsigned* a, const unsigned* b){
  asm volatile(
    "mma.sync.aligned.m16n8k8.row.col.f32.tf32.tf32.f32 "
    "{%0,%1,%2,%3}, {%4,%5,%6,%7}, {%8,%9}, {%0,%1,%2,%3};"
    : "+f"(d[0]), "+f"(d[1]), "+f"(d[2]), "+f"(d[3])
    : "r"(a[0]), "r"(a[1]), "r"(a[2]), "r"(a[3]), "r"(b[0]), "r"(b[1]));
}

// ---------------- stage 1: maxpool + Haar DWT -> tokens ----------------
__global__ void frontend_kernel(const float* __restrict__ x){
  int idx = blockIdx.x*blockDim.x + threadIdx.x;
  if (idx >= BATCH*640*256) return;
  int p = idx & 255;
  int n = (idx >> 8) % 640;
  int b = idx / (640*256);
  int i = p >> 4, j = p & 15;
  float val;
  if (n < 128){
    const float* xp = x + (size_t)(b*128+n)*1024;
    float m = -INFINITY;
    int r0 = 2*i-1, c0 = 2*j-1;
    #pragma unroll
    for (int dr=0;dr<3;dr++){
      int r = r0+dr; if (r<0 || r>31) continue;
      #pragma unroll
      for (int dc=0;dc<3;dc++){
        int cc = c0+dc; if (cc<0 || cc>31) continue;
        m = fmaxf(m, xp[r*32+cc]);
      }
    }
    val = m;
  } else {
    int g  = (n-128)>>7;
    int ch = (n-128)&127;
    const float* xp = x + (size_t)(b*128+ch)*1024;
    float a  = xp[(2*i)*32 + 2*j];
    float bb = xp[(2*i)*32 + 2*j+1];
    float c  = xp[(2*i+1)*32 + 2*j];
    float d  = xp[(2*i+1)*32 + 2*j+1];
    if      (g==0) val = (a+bb+c+d)*0.5f;
    else if (g==1) val = (a-bb+c-d)*0.5f;
    else if (g==2) val = (a+bb-c-d)*0.5f;
    else           val = (a-bb-c+d)*0.5f;
  }
  g_tokens[idx] = val;
}

// ---------------- stage 2: fused qk/v GEMM (fp32 exact), head-split epilogue ----------------
__global__ __launch_bounds__(256) void gemm_qkv_kernel(const float* __restrict__ Wqk,
                                                       const float* __restrict__ Wv){
  __shared__ float As [32][64];
  __shared__ float B1s[32][64];
  __shared__ float B2s[32][64];
  int tid = threadIdx.x;
  int m0 = blockIdx.y*64, n0 = blockIdx.x*64;
  int ty = tid>>4, tx = tid&15;
  float acc1[4][4], acc2[4][4];
  #pragma unroll
  for (int i=0;i<4;i++)
    #pragma unroll
    for (int j=0;j<4;j++){ acc1[i][j]=0.f; acc2[i][j]=0.f; }

  for (int k0=0;k0<256;k0+=32){
    int am = tid>>2, akq = tid&3;
    const float* asrc = g_tokens + (size_t)(m0+am)*256 + k0 + akq*8;
    float4 a0 = *(const float4*)asrc;
    float4 a1 = *(const float4*)(asrc+4);
    As[akq*8+0][am]=a0.x; As[akq*8+1][am]=a0.y; As[akq*8+2][am]=a0.z; As[akq*8+3][am]=a0.w;
    As[akq*8+4][am]=a1.x; As[akq*8+5][am]=a1.y; As[akq*8+6][am]=a1.z; As[akq*8+7][am]=a1.w;

    int bk = tid>>3, bnq = tid&7;
    const float* b1src = Wqk + (size_t)(k0+bk)*256 + n0 + bnq*8;
    const float* b2src = Wv  + (size_t)(k0+bk)*256 + n0 + bnq*8;
    *(float4*)&B1s[bk][bnq*8]   = *(const float4*)b1src;
    *(float4*)&B1s[bk][bnq*8+4] = *(const float4*)(b1src+4);
    *(float4*)&B2s[bk][bnq*8]   = *(const float4*)b2src;
    *(float4*)&B2s[bk][bnq*8+4] = *(const float4*)(b2src+4);
    __syncthreads();

    #pragma unroll
    for (int k=0;k<32;k++){
      float4 av = *(float4*)&As [k][ty*4];
      float4 b1 = *(float4*)&B1s[k][tx*4];
      float4 b2 = *(float4*)&B2s[k][tx*4];
      float aa[4]  = {av.x,av.y,av.z,av.w};
      float bb1[4] = {b1.x,b1.y,b1.z,b1.w};
      float bb2[4] = {b2.x,b2.y,b2.z,b2.w};
      #pragma unroll
      for (int i2=0;i2<4;i2++)
        #pragma unroll
        for (int j2=0;j2<4;j2++){
          acc1[i2][j2] += aa[i2]*bb1[j2];
          acc2[i2][j2] += aa[i2]*bb2[j2];
        }
    }
    __syncthreads();
  }
  #pragma unroll
  for (int i2=0;i2<4;i2++){
    int row = m0 + ty*4 + i2;
    int b = row/640, tok = row%640;
    #pragma unroll
    for (int j2=0;j2<4;j2++){
      int col = n0 + tx*4 + j2;
      int head = col>>5, dh = col&31;
      size_t o = ((size_t)(b*8+head)*640 + tok)*32 + dh;
      g_qk[o] = acc1[i2][j2];
      g_v [o] = acc2[i2][j2];
    }
  }
}

// ---------------- stage 3a: LSH bucket ids (fp32 exact) ----------------
__global__ void bucket_kernel(const float* __restrict__ rot){
  __shared__ float s_rot[32*NHASH*5];
  for (int i=threadIdx.x;i<1280;i+=blockDim.x) s_rot[i]=rot[i];
  __syncthreads();
  int idx = blockIdx.x*blockDim.x + threadIdx.x;
  if (idx >= BHDIM*NHASH*T) return;
  int pos = idx % 640;
  int h   = (idx/640) & 7;
  int bh  = idx / (NHASH*T);
  const float* q = g_qk + ((size_t)bh*640 + pos)*32;
  float r[5] = {0.f,0.f,0.f,0.f,0.f};
  #pragma unroll 8
  for (int f=0;f<32;f++){
    float qf = q[f];
    const float* rp = s_rot + f*40 + h*5;
    #pragma unroll
    for (int i=0;i<5;i++) r[i] += qf*rp[i];
  }
  float best = r[0]; int bi = 0;
  #pragma unroll
  for (int i=1;i<5;i++) if (r[i] > best){ best=r[i]; bi=i; }
  #pragma unroll
  for (int i=0;i<5;i++){ float v = -r[i]; if (v > best){ best=v; bi=5+i; } }
  g_bucket[idx] = bi;
}

// ---------------- stage 3b: stable counting sort per (bh, hash) ----------------
__global__ __launch_bounds__(320) void sort_kernel(){
  __shared__ int cnt[10], off[10];
  int bhh = blockIdx.x;
  const int* bk = g_bucket + bhh*640;
  int w = threadIdx.x>>5, lane = threadIdx.x&31;
  int count = 0;
  for (int base=0;base<640;base+=32){
    int bb = bk[base+lane];
    unsigned mask = __ballot_sync(0xffffffffu, bb==w);
    count += __popc(mask);
  }
  if (lane==0) cnt[w] = count;
  __syncthreads();
  if (threadIdx.x==0){
    int run=0;
    for (int b=0;b<10;b++){ off[b]=run; run+=cnt[b]; }
  }
  __syncthreads();
  int base_off = off[w]; int run = 0;
  int* out = g_sorted + bhh*640;
  for (int base=0;base<640;base+=32){
    int bb = bk[base+lane];
    unsigned mask = __ballot_sync(0xffffffffu, bb==w);
    if (bb==w){
      int slot = base_off + run + __popc(mask & ((1u<<lane)-1u));
      out[slot] = base+lane;
    }
    run += __popc(mask);
  }
}

// ---------------- stage 4: chunked attention, tf32 mma.sync ----------------
// smem: s_p [64][132] (33792B); s_q ([64][36]) and s_k ([128][36]) alias into s_p
// region (dead after dots). s_v [128][40] (20480B). reductions + token ids.
#define Q_PAD 36
#define K_PAD 36
#define V_PAD 40
#define P_PAD 132
#define SMEM_ATTN ((64*P_PAD + 128*V_PAD + 2*128)*4 + (64+128)*4)

__global__ __launch_bounds__(256) void attn_kernel(){
  extern __shared__ char smem_raw[];
  float* s_p    = (float*)smem_raw;          // [64][132]
  float* s_q    = s_p;                       // [64][36]  alias
  float* s_k    = s_p + 64*Q_PAD;            // [128][36] alias (2304..6912 floats)
  float* s_v    = s_p + 64*P_PAD;            // [128][40]
  float* s_redm = s_v + 128*V_PAD;           // [2][64]
  float* s_reds = s_redm + 128;              // [2][64]
  int*   s_qt   = (int*)(s_reds + 128);      // [64]
  int*   s_kt   = s_qt + 64;                 // [128]

  int tid = threadIdx.x;
  int blk = blockIdx.x;
  int bh = blk / NCHUNK, c = blk % NCHUNK;
  int h  = c / 10;
  int pc = (c + NCHUNK - 1) % NCHUNK;
  int ph = pc / 10;
  const int* sortedbh = g_sorted + bh*NHASH*T;

  if (tid < 64)
    s_qt[tid] = sortedbh[h*640 + (c%10)*64 + tid];
  else if (tid < 192){
    int j = tid - 64;
    s_kt[j] = (j < 64) ? sortedbh[h*640 + (c%10)*64 + j]
                       : sortedbh[ph*640 + (pc%10)*64 + (j-64)];
  }
  __syncthreads();

  // Q row-major [64][36]
  {
    int i = tid >> 2, f0 = (tid & 3) * 8;
    const float* src = g_qk + ((size_t)bh*640 + s_qt[i])*32 + f0;
    *(float4*)&s_q[i*Q_PAD + f0]     = *(const float4*)src;
    *(float4*)&s_q[i*Q_PAD + f0 + 4] = *(const float4*)(src+4);
  }
  // K row-major [128][36], normalized
  {
    int j = tid >> 1, fh = (tid & 1) * 16;
    const float* src = g_qk + ((size_t)bh*640 + s_kt[j])*32 + fh;
    float buf[16]; float ss = 0.f;
    #pragma unroll
    for (int u=0;u<16;u+=4){
      float4 a = *(const float4*)(src+u);
      buf[u]=a.x; buf[u+1]=a.y; buf[u+2]=a.z; buf[u+3]=a.w;
      ss += a.x*a.x + a.y*a.y + a.z*a.z + a.w*a.w;
    }
    ss += __shfl_xor_sync(0xffffffffu, ss, 1);
    float inv = 1.f / fmaxf(sqrtf(ss), 1e-6f);
    #pragma unroll
    for (int u=0;u<16;u+=4)
      *(float4*)&s_k[j*K_PAD + fh + u] =
        make_float4(buf[u]*inv, buf[u+1]*inv, buf[u+2]*inv, buf[u+3]*inv);
  }
  // V row-major [128][40]
  {
    int j = tid >> 1, fh = (tid & 1) * 16;
    const float* src = g_v + ((size_t)bh*640 + s_kt[j])*32 + fh;
    #pragma unroll
    for (int u=0;u<16;u+=4)
      *(float4*)&s_v[j*V_PAD + fh + u] = *(const float4*)(src+u);
  }
  __syncthreads();

  // warp tiling: wm in 0..3 (16 query rows), wn in 0..1 (64-key half)
  int warp = tid >> 5, lane = tid & 31;
  int wm = warp & 3, wn = warp >> 2;
  int g = lane >> 2, tig = lane & 3;
  int m0 = wm * 16;
  int rA = m0 + g, rB = m0 + g + 8;

  // ---- dots: S(16x64 per warp) = Q x K^T, tf32 mma ----
  float acc[8][4];
  #pragma unroll
  for (int nt=0;nt<8;nt++)
    #pragma unroll
    for (int u=0;u<4;u++) acc[nt][u] = 0.f;

  #pragma unroll
  for (int k0=0;k0<32;k0+=8){
    unsigned af[4];
    af[0] = __float_as_uint(s_q[rA*Q_PAD + k0 + tig]);
    af[1] = __float_as_uint(s_q[rB*Q_PAD + k0 + tig]);
    af[2] = __float_as_uint(s_q[rA*Q_PAD + k0 + tig + 4]);
    af[3] = __float_as_uint(s_q[rB*Q_PAD + k0 + tig + 4]);
    #pragma unroll
    for (int nt=0;nt<8;nt++){
      int n0 = wn*64 + nt*8;
      unsigned bf[2];
      bf[0] = __float_as_uint(s_k[(n0+g)*K_PAD + k0 + tig]);
      bf[1] = __float_as_uint(s_k[(n0+g)*K_PAD + k0 + tig + 4]);
      mma_tf32(acc[nt], af, bf);
    }
  }

  // scale + self-mask
  int qtA = s_qt[rA], qtB = s_qt[rB];
  #pragma unroll
  for (int nt=0;nt<8;nt++){
    int n0 = wn*64 + nt*8;
    int kt0 = s_kt[n0 + 2*tig], kt1 = s_kt[n0 + 2*tig + 1];
    acc[nt][0] = (kt0==qtA) ? -50000.f : acc[nt][0]*0.17677669529663687f;
    acc[nt][1] = (kt1==qtA) ? -50000.f : acc[nt][1]*0.17677669529663687f;
    acc[nt][2] = (kt0==qtB) ? -50000.f : acc[nt][2]*0.17677669529663687f;
    acc[nt][3] = (kt1==qtB) ? -50000.f : acc[nt][3]*0.17677669529663687f;
  }

  // partial row max/sum over this warp's 64 cols
  float mA=-INFINITY, mB=-INFINITY;
  #pragma unroll
  for (int nt=0;nt<8;nt++){
    mA = fmaxf(mA, fmaxf(acc[nt][0], acc[nt][1]));
    mB = fmaxf(mB, fmaxf(acc[nt][2], acc[nt][3]));
  }
  #pragma unroll
  for (int o=1;o<=2;o<<=1){
    mA = fmaxf(mA, __shfl_xor_sync(0xffffffffu, mA, o, 4));
    mB = fmaxf(mB, __shfl_xor_sync(0xffffffffu, mB, o, 4));
  }
  float sA=0.f, sB=0.f;
  #pragma unroll
  for (int nt=0;nt<8;nt++){
    sA += __expf(acc[nt][0]-mA) + __expf(acc[nt][1]-mA);
    sB += __expf(acc[nt][2]-mB) + __expf(acc[nt][3]-mB);
  }
  #pragma unroll
  for (int o=1;o<=2;o<<=1){
    sA += __shfl_xor_sync(0xffffffffu, sA, o, 4);
    sB += __shfl_xor_sync(0xffffffffu, sB, o, 4);
  }
  if (tig == 0){
    s_redm[wn*64 + rA] = mA;  s_reds[wn*64 + rA] = sA;
    s_redm[wn*64 + rB] = mB;  s_reds[wn*64 + rB] = sB;
  }
  __syncthreads();   // also: all dots-reads of s_q/s_k complete past this point

  float lseA, lseB;
  {
    float m0A = s_redm[rA], m1A = s_redm[64+rA];
    float mm = fmaxf(m0A, m1A);
    float ss = s_reds[rA]*__expf(m0A-mm) + s_reds[64+rA]*__expf(m1A-mm);
    lseA = mm + __logf(ss);
    float m0B = s_redm[rB], m1B = s_redm[64+rB];
    mm = fmaxf(m0B, m1B);
    ss = s_reds[rB]*__expf(m0B-mm) + s_reds[64+rB]*__expf(m1B-mm);
    lseB = mm + __logf(ss);
  }
  if (wn == 0 && tig == 0){
    g_logit[(bh*NHASH+h)*T + qtA] = lseA;
    g_logit[(bh*NHASH+h)*T + qtB] = lseB;
  }

  // probs into s_p (overwrites s_q/s_k region)
  #pragma unroll
  for (int nt=0;nt<8;nt++){
    int n0 = wn*64 + nt*8;
    *(float2*)&s_p[rA*P_PAD + n0 + 2*tig] =
      make_float2(__expf(acc[nt][0]-lseA), __expf(acc[nt][1]-lseA));
    *(float2*)&s_p[rB*P_PAD + n0 + 2*tig] =
      make_float2(__expf(acc[nt][2]-lseB), __expf(acc[nt][3]-lseB));
  }
  __syncthreads();

  // ---- PV: O(16x16 per warp) = P(16x128) x V(128x32), tf32 mma ----
  float o0[4] = {0.f,0.f,0.f,0.f};
  float o1[4] = {0.f,0.f,0.f,0.f};
  #pragma unroll 4
  for (int k0=0;k0<128;k0+=8){
    unsigned af[4];
    af[0] = __float_as_uint(s_p[rA*P_PAD + k0 + tig]);
    af[1] = __float_as_uint(s_p[rB*P_PAD + k0 + tig]);
    af[2] = __float_as_uint(s_p[rA*P_PAD + k0 + tig + 4]);
    af[3] = __float_as_uint(s_p[rB*P_PAD + k0 + tig + 4]);
    unsigned bf0[2], bf1[2];
    int d0 = wn*16;
    bf0[0] = __float_as_uint(s_v[(k0+tig)*V_PAD   + d0 + g]);
    bf0[1] = __float_as_uint(s_v[(k0+tig+4)*V_PAD + d0 + g]);
    bf1[0] = __float_as_uint(s_v[(k0+tig)*V_PAD   + d0 + 8 + g]);
    bf1[1] = __float_as_uint(s_v[(k0+tig+4)*V_PAD + d0 + 8 + g]);
    mma_tf32(o0, af, bf0);
    mma_tf32(o1, af, bf1);
  }
  {
    size_t base = (size_t)(bh*NHASH+h)*T;
    float* dA = g_ohash + (base + qtA)*32;
    float* dB = g_ohash + (base + qtB)*32;
    int d0 = wn*16;
    *(float2*)(dA + d0 + 2*tig)     = make_float2(o0[0], o0[1]);
    *(float2*)(dB + d0 + 2*tig)     = make_float2(o0[2], o0[3]);
    *(float2*)(dA + d0 + 8 + 2*tig) = make_float2(o1[0], o1[1]);
    *(float2*)(dB + d0 + 8 + 2*tig) = make_float2(o1[2], o1[3]);
  }
}

// ---------------- stage 5: combine hashes, merge heads (float4) ----------------
__global__ void combine_kernel(){
  int idx = blockIdx.x*blockDim.x + threadIdx.x;
  if (idx >= BHDIM*T*8) return;
  int dq  = idx & 7;
  int pos = (idx >> 3) % 640;
  int bh  = idx / (640*8);
  float l[NHASH];
  #pragma unroll
  for (int h=0;h<NHASH;h++) l[h] = g_logit[(bh*NHASH+h)*T + pos];
  float m = l[0];
  #pragma unroll
  for (int h=1;h<NHASH;h++) m = fmaxf(m, l[h]);
  float s = 0.f;
  float e[NHASH];
  #pragma unroll
  for (int h=0;h<NHASH;h++){ e[h] = __expf(l[h]-m); s += e[h]; }
  float inv = 1.f/s;
  float4 acc = make_float4(0.f,0.f,0.f,0.f);
  #pragma unroll
  for (int h=0;h<NHASH;h++){
    float w = e[h]*inv;
    float4 v = *(const float4*)(g_ohash + ((size_t)(bh*NHASH+h)*T + pos)*32 + dq*4);
    acc.x += w*v.x; acc.y += w*v.y; acc.z += w*v.z; acc.w += w*v.w;
  }
  int b = bh>>3, head = bh&7;
  *(float4*)(g_omerged + ((size_t)b*640 + pos)*256 + head*32 + dq*4) = acc;
}

// ---------------- stage 6: output GEMM + bias (fp32) ----------------
__global__ __launch_bounds__(256) void gemm_out_kernel(const float* __restrict__ W,
                                                       const float* __restrict__ bias,
                                                       float* __restrict__ out){
  __shared__ float As[32][64];
  __shared__ float Bs[32][64];
  int tid = threadIdx.x;
  int m0 = blockIdx.y*64, n0 = blockIdx.x*64;
  int ty = tid>>4, tx = tid&15;
  float acc[4][4];
  #pragma unroll
  for (int i=0;i<4;i++)
    #pragma unroll
    for (int j=0;j<4;j++) acc[i][j]=0.f;

  for (int k0=0;k0<256;k0+=32){
    int am = tid>>2, akq = tid&3;
    const float* asrc = g_omerged + (size_t)(m0+am)*256 + k0 + akq*8;
    float4 a0 = *(const float4*)asrc;
    float4 a1 = *(const float4*)(asrc+4);
    As[akq*8+0][am]=a0.x; As[akq*8+1][am]=a0.y; As[akq*8+2][am]=a0.z; As[akq*8+3][am]=a0.w;
    As[akq*8+4][am]=a1.x; As[akq*8+5][am]=a1.y; As[akq*8+6][am]=a1.z; As[akq*8+7][am]=a1.w;

    int bk = tid>>3, bnq = tid&7;
    const float* bsrc = W + (size_t)(k0+bk)*256 + n0 + bnq*8;
    *(float4*)&Bs[bk][bnq*8]   = *(const float4*)bsrc;
    *(float4*)&Bs[bk][bnq*8+4] = *(const float4*)(bsrc+4);
    __syncthreads();

    #pragma unroll
    for (int k=0;k<32;k++){
      float4 av = *(float4*)&As[k][ty*4];
      float4 bv = *(float4*)&Bs[k][tx*4];
      float aa[4] = {av.x,av.y,av.z,av.w};
      float bb[4] = {bv.x,bv.y,bv.z,bv.w};
      #pragma unroll
      for (int i2=0;i2<4;i2++)
        #pragma unroll
        for (int j2=0;j2<4;j2++) acc[i2][j2] += aa[i2]*bb[j2];
    }
    __syncthreads();
  }
  #pragma unroll
  for (int i2=0;i2<4;i2++){
    int row = m0 + ty*4 + i2;
    #pragma unroll
    for (int j2=0;j2<4;j2++){
      int col = n0 + tx*4 + j2;
      out[(size_t)row*256 + col] = acc[i2][j2] + bias[col];
    }
  }
}

// ---------------- launch ----------------
extern "C" void kernel_launch(void* const* d_in, const int* in_sizes, int n_in,
                              void* d_out, int out_size){
  const float* x     = (const float*)d_in[0];
  const float* w_qk  = (const float*)d_in[1];
  const float* w_v   = (const float*)d_in[2];
  const float* w_out = (const float*)d_in[3];
  const float* b_out = (const float*)d_in[4];
  const float* rot   = (const float*)d_in[5];
  float* out = (float*)d_out;

  frontend_kernel<<<(BATCH*640*256+255)/256, 256>>>(x);
  gemm_qkv_kernel<<<dim3(4,160), 256>>>(w_qk, w_v);
  bucket_kernel<<<(BHDIM*NHASH*T+255)/256, 256>>>(rot);
  sort_kernel<<<BHDIM*NHASH, 320>>>();
  cudaFuncSetAttribute(attn_kernel, cudaFuncAttributeMaxDynamicSharedMemorySize, SMEM_ATTN);
  attn_kernel<<<BHDIM*NCHUNK, 256, SMEM_ATTN>>>();
  combine_kernel<<<(BHDIM*T*8+255)/256, 256>>>();
  gemm_out_kernel<<<dim3(4,160), 256>>>(w_out, b_out, out);
}